// round 3
// baseline (speedup 1.0000x reference)
#include <cuda_runtime.h>
#include <cstdint>

#define IN_DIM 1024     // 2*L1
#define LXD    32
#define NBUCK  8
#define MAXB   65536
#define BK     32
#define MTILE  256
#define NTHR   256
#define NSTEP  (IN_DIM / BK)               // 32
#define NVT    (NBUCK * (MAXB / MTILE))    // 2048 virtual tiles
#define NWORK  304                         // 2 CTAs/SM * 152 SMs (GB300)

// ---------------- device scratch (no allocation allowed) ----------------
__device__ float g_WcT[NBUCK * IN_DIM * LXD];   // [bucket][k][j] : w0 + w_fact, transposed
__device__ int   g_cnt[NBUCK];
__device__ int   g_list[NBUCK * MAXB];
__device__ int   g_ctr;                         // work-stealing tile counter

// ---------------- small PTX helpers ----------------
__device__ __forceinline__ unsigned sptr(const void* p) {
    return (unsigned)__cvta_generic_to_shared(p);
}
__device__ __forceinline__ void cp8(void* dst, const void* src) {
    asm volatile("cp.async.ca.shared.global [%0], [%1], 8;\n" :: "r"(sptr(dst)), "l"(src));
}
__device__ __forceinline__ void cp16(void* dst, const void* src) {
    asm volatile("cp.async.cg.shared.global [%0], [%1], 16;\n" :: "r"(sptr(dst)), "l"(src));
}
__device__ __forceinline__ void cp_commit() { asm volatile("cp.async.commit_group;\n"); }
template<int N> __device__ __forceinline__ void cp_wait() {
    asm volatile("cp.async.wait_group %0;\n" :: "n"(N));
}
__device__ __forceinline__ unsigned long long pack2(float x) {
    unsigned long long r;
    asm("mov.b64 %0, {%1, %2};" : "=l"(r) : "f"(x), "f"(x));
    return r;
}
__device__ __forceinline__ void fma2(unsigned long long& d,
                                     unsigned long long a, unsigned long long b) {
    asm("fma.rn.f32x2 %0, %1, %2, %0;" : "+l"(d) : "l"(a), "l"(b));
}
__device__ __forceinline__ float2 unpack2(unsigned long long a) {
    float2 v;
    asm("mov.b64 {%0, %1}, %2;" : "=f"(v.x), "=f"(v.y) : "l"(a));
    return v;
}

// ---------------- kernel 1: zero counters + build combined transposed weights ----------------
__global__ void prep_kernel(const float* __restrict__ w0, const float* __restrict__ w_fact) {
    int idx = blockIdx.x * blockDim.x + threadIdx.x;   // NBUCK*IN_DIM*LXD = 262144
    if (idx < NBUCK * IN_DIM * LXD) {
        int j = idx & (LXD - 1);
        int k = (idx >> 5) & (IN_DIM - 1);
        int b = idx >> 15;
        g_WcT[idx] = w0[(b * LXD + j) * IN_DIM + k] + w_fact[j * IN_DIM + k];
    }
    if (blockIdx.x == 0 && threadIdx.x < NBUCK) g_cnt[threadIdx.x] = 0;
    if (blockIdx.x == 0 && threadIdx.x == 0)    g_ctr = 0;
}

// ---------------- kernel 2: bin rows by bucket (warp-aggregated atomics) ----------------
// ls_indices is int32 on the wire (JAX without x64 aliases jnp.int64 -> int32).
__global__ void bin_kernel(const int* __restrict__ ls, int B) {
    int i = blockIdx.x * blockDim.x + threadIdx.x;
    if (i >= B) return;
    int b = ls[i] & (NBUCK - 1);
    unsigned active = __activemask();
    unsigned m = __match_any_sync(active, b);
    int lane = threadIdx.x & 31;
    int leader = __ffs(m) - 1;
    int rank = __popc(m & ((1u << lane) - 1u));
    int base = 0;
    if (lane == leader) base = atomicAdd(&g_cnt[b], __popc(m));
    base = __shfl_sync(m, base, leader);
    g_list[b * MAXB + base + rank] = i;
}

// ---------------- kernel 3: persistent binned GEMM + fused MLP ----------------
struct __align__(16) Smem {
    float Ws[2][BK][LXD];             // [kk][j], 16B-aligned rows
    float Xs[2][MTILE][BK + 2];       // stride 34 floats (8B-aligned rows, 2-way conflict)
    const float* xptr[MTILE];
    int   perm[MTILE];
    float w1T[LXD * LXD];             // w1 transposed: [i][j]
    float b0s[LXD], b1s[LXD], w2s[LXD];
    float b2s;
    int   cur_vt;
};

__device__ __forceinline__ void process_row(const Smem* S, const unsigned long long* acc,
                                            int row, float* __restrict__ out) {
    if (row < 0) return;
    float h[LXD];
#pragma unroll
    for (int q = 0; q < LXD / 2; ++q) {
        float2 v = unpack2(acc[q]);
        h[2 * q] = v.x; h[2 * q + 1] = v.y;
    }
    float h2[LXD];
#pragma unroll
    for (int j = 0; j < LXD; ++j) h2[j] = S->b1s[j];
#pragma unroll
    for (int i = 0; i < LXD; ++i) {
        float xi = h[i] + S->b0s[i];
        xi = fminf(fmaxf(xi, 0.0f), 1.0f);
        const float* wr = &S->w1T[i * LXD];
#pragma unroll
        for (int j = 0; j < LXD; ++j) h2[j] = fmaf(xi, wr[j], h2[j]);
    }
    float o = S->b2s;
#pragma unroll
    for (int j = 0; j < LXD; ++j) {
        float c = fminf(fmaxf(h2[j], 0.0f), 1.0f);
        o = fmaf(c, S->w2s[j], o);
    }
    out[row] = o;
}

__global__ void __launch_bounds__(NTHR, 2)
main_kernel(const float* __restrict__ x,
            const float* __restrict__ b0, const float* __restrict__ b1,
            const float* __restrict__ w1, const float* __restrict__ w2,
            const float* __restrict__ b2,
            float* __restrict__ out, int B) {
    extern __shared__ char smem_raw[];
    Smem* S = reinterpret_cast<Smem*>(smem_raw);

    const int t  = threadIdx.x;
    const int k2 = t & 15;       // 16 x 2-float chunks cover BK=32 k
    const int rb = t >> 4;       // 16 row-groups

    while (true) {
        // ---- steal a virtual tile: vt = tile*NBUCK + bucket (real tiles first) ----
        if (t == 0) S->cur_vt = atomicAdd(&g_ctr, 1);
        __syncthreads();
        const int vt = S->cur_vt;
        __syncthreads();
        if (vt >= NVT) return;
        const int b    = vt & (NBUCK - 1);
        const int tile = vt >> 3;
        const int cnt  = g_cnt[b];
        const int start = tile * MTILE;
        if (start >= cnt) continue;

        // ---- stage per-CTA metadata + small weights ----
        {
            int g = start + t;
            int ridx = (g < cnt) ? g_list[b * MAXB + g] : -1;
            S->perm[t] = ridx;
            S->xptr[t] = x + (size_t)(ridx < 0 ? 0 : ridx) * IN_DIM;
        }
        for (int idx = t; idx < LXD * LXD; idx += NTHR) {
            int i = idx >> 5, j = idx & 31;
            S->w1T[idx] = w1[(b * LXD + j) * LXD + i];
        }
        if (t < LXD) {
            S->b0s[t] = b0[b * LXD + t];
            S->b1s[t] = b1[b * LXD + t];
            S->w2s[t] = w2[b * LXD + t];
        }
        if (t == 32) S->b2s = b2[b];
        __syncthreads();

        const float* wct = g_WcT + (size_t)b * IN_DIM * LXD;

        // ---- async loader for one K-step ----
        auto load_step = [&](int stage, int k0) {
#pragma unroll
            for (int p = 0; p < MTILE / 16; ++p) {
                int r = p * 16 + rb;
                cp8(&S->Xs[stage][r][k2 * 2], S->xptr[r] + k0 + k2 * 2);
            }
            cp16(&S->Ws[stage][0][0] + t * 4, wct + (size_t)k0 * LXD + t * 4);
            cp_commit();
        };

        unsigned long long acc[LXD / 2];
#pragma unroll
        for (int q = 0; q < LXD / 2; ++q) acc[q] = 0ull;

        load_step(0, 0);

#pragma unroll 1
        for (int s = 0; s < NSTEP; ++s) {
            const int stage = s & 1;
            if (s + 1 < NSTEP) {
                load_step(stage ^ 1, (s + 1) * BK);
                cp_wait<1>();
            } else {
                cp_wait<0>();
            }
            __syncthreads();

#pragma unroll 8
            for (int kk = 0; kk < BK; ++kk) {
                unsigned long long X0 = pack2(S->Xs[stage][t][kk]);
                const ulonglong2* wp =
                    reinterpret_cast<const ulonglong2*>(&S->Ws[stage][kk][0]);
#pragma unroll
                for (int q = 0; q < 8; ++q) {
                    ulonglong2 w = wp[q];
                    fma2(acc[2 * q],     X0, w.x);
                    fma2(acc[2 * q + 1], X0, w.y);
                }
            }
            __syncthreads();
        }

        // ---- fused layer1 + layer2 epilogue ----
        process_row(S, acc, S->perm[t], out);
        __syncthreads();   // protect smem before next stolen tile's prologue
    }
}

// ---------------- launch ----------------
extern "C" void kernel_launch(void* const* d_in, const int* in_sizes, int n_in,
                              void* d_out, int out_size) {
    const float* x      = (const float*)d_in[0];
    const int*   ls     = (const int*)d_in[1];   // int32 on the wire
    const float* w_fact = (const float*)d_in[2];
    const float* w0     = (const float*)d_in[3];
    const float* b0     = (const float*)d_in[4];
    const float* w1     = (const float*)d_in[5];
    const float* b1     = (const float*)d_in[6];
    const float* w2     = (const float*)d_in[7];
    const float* b2     = (const float*)d_in[8];
    float*       out    = (float*)d_out;

    const int B = in_sizes[0] / IN_DIM;

    // 1. zero counters + precompute combined transposed weights
    prep_kernel<<<(NBUCK * IN_DIM * LXD + 255) / 256, 256>>>(w0, w_fact);
    // 2. bin rows by bucket
    bin_kernel<<<(B + 255) / 256, 256>>>(ls, B);
    // 3. persistent binned GEMM + fused MLP (work-stealing over virtual tiles)
    static const size_t smem_bytes = sizeof(Smem);
    cudaFuncSetAttribute(main_kernel, cudaFuncAttributeMaxDynamicSharedMemorySize,
                         (int)smem_bytes);
    main_kernel<<<NWORK, NTHR, smem_bytes>>>(x, b0, b1, w1, w2, b2, out, B);
}

// round 4
// speedup vs baseline: 2.4690x; 2.4690x over previous
#include <cuda_runtime.h>
#include <cstdint>

#define IN_DIM 1024     // 2*L1
#define LXD    32
#define NBUCK  8
#define MAXB   65536
#define BK     32       // K per pipeline step
#define MTILE  256
#define NTHR   256
#define NSTEP  (IN_DIM / BK)   // 32
#define XSTR   40       // Xs row stride in floats (8B aligned, low conflict)

// ---------------- device scratch ----------------
// Weight fragments: [b][step][split(hi/lo)][kf][nf][lane*2+r] as u32 bf16x2 pairs
__device__ uint32_t g_Wfrag[NBUCK * 32 * 2 * 2 * 4 * 64];   // 1 MB
__device__ int      g_cnt[NBUCK];
__device__ int      g_list[NBUCK * MAXB];

// ---------------- PTX helpers ----------------
__device__ __forceinline__ unsigned sptr(const void* p) {
    return (unsigned)__cvta_generic_to_shared(p);
}
__device__ __forceinline__ void cp8(void* dst, const void* src) {
    asm volatile("cp.async.ca.shared.global [%0], [%1], 8;\n" :: "r"(sptr(dst)), "l"(src));
}
__device__ __forceinline__ void cp16(void* dst, const void* src) {
    asm volatile("cp.async.cg.shared.global [%0], [%1], 16;\n" :: "r"(sptr(dst)), "l"(src));
}
__device__ __forceinline__ void cp_commit() { asm volatile("cp.async.commit_group;\n"); }
template<int N> __device__ __forceinline__ void cp_wait() {
    asm volatile("cp.async.wait_group %0;\n" :: "n"(N));
}
// pack two f32 -> bf16x2 (upper = hi_src, lower = lo_src)
__device__ __forceinline__ uint32_t cvt_pack(float hi_src, float lo_src) {
    uint32_t r;
    asm("cvt.rn.bf16x2.f32 %0, %1, %2;" : "=r"(r) : "f"(hi_src), "f"(lo_src));
    return r;
}
__device__ __forceinline__ void mma_bf16(float c[4], const uint32_t a[4],
                                         uint32_t b0, uint32_t b1) {
    asm("mma.sync.aligned.m16n8k16.row.col.f32.bf16.bf16.f32 "
        "{%0,%1,%2,%3},{%4,%5,%6,%7},{%8,%9},{%0,%1,%2,%3};"
        : "+f"(c[0]), "+f"(c[1]), "+f"(c[2]), "+f"(c[3])
        : "r"(a[0]), "r"(a[1]), "r"(a[2]), "r"(a[3]), "r"(b0), "r"(b1));
}
// split a float pair (p.x = k, p.y = k+1) into bf16x2 hi + bf16x2 lo
__device__ __forceinline__ void split2(float2 p, uint32_t& h, uint32_t& l) {
    h = cvt_pack(p.y, p.x);
    float e0 = p.x - __uint_as_float(h << 16);
    float e1 = p.y - __uint_as_float(h & 0xffff0000u);
    l = cvt_pack(e1, e0);
}

// ---------------- kernel 1: build bf16 hi/lo weight fragments + zero counters ----------------
__global__ void prep_kernel(const float* __restrict__ w0, const float* __restrict__ w_fact) {
    int tid = blockIdx.x * blockDim.x + threadIdx.x;   // NBUCK*LXD*512 = 131072
    if (tid < NBUCK * LXD * 512) {
        int kp = tid & 511;            // k pair index
        int j  = (tid >> 9) & 31;      // output column n
        int b  = tid >> 14;            // bucket
        int k0 = kp * 2;
        float x0 = w0[(b * LXD + j) * IN_DIM + k0]     + w_fact[j * IN_DIM + k0];
        float x1 = w0[(b * LXD + j) * IN_DIM + k0 + 1] + w_fact[j * IN_DIM + k0 + 1];
        uint32_t h, l;
        split2(make_float2(x0, x1), h, l);
        int step = k0 >> 5, kk = k0 & 31;
        int kf = kk >> 4, kr = kk & 15;
        int r = kr >> 3;
        int lane = ((j & 7) << 2) + ((kr & 7) >> 1);
        int nf = j >> 3;
        int base = ((((b * 32 + step) * 2 + 0) * 2 + kf) * 4 + nf) * 64 + lane * 2 + r;
        g_Wfrag[base]       = h;       // split 0 (hi)
        g_Wfrag[base + 512] = l;       // split 1 (lo), stride 2*4*64
    }
    if (blockIdx.x == 0 && threadIdx.x < NBUCK) g_cnt[threadIdx.x] = 0;
}

// ---------------- kernel 2: bin rows by bucket ----------------
// ls_indices is int32 on the wire (JAX x64 disabled).
__global__ void bin_kernel(const int* __restrict__ ls, int B) {
    int i = blockIdx.x * blockDim.x + threadIdx.x;
    if (i >= B) return;
    int b = ls[i] & (NBUCK - 1);
    unsigned active = __activemask();
    unsigned m = __match_any_sync(active, b);
    int lane = threadIdx.x & 31;
    int leader = __ffs(m) - 1;
    int rank = __popc(m & ((1u << lane) - 1u));
    int base = 0;
    if (lane == leader) base = atomicAdd(&g_cnt[b], __popc(m));
    base = __shfl_sync(m, base, leader);
    g_list[b * MAXB + base + rank] = i;
}

// ---------------- kernel 3: tensor-core binned GEMM + fused MLP ----------------
struct __align__(16) Smem {
    float    Xs[2][MTILE][XSTR];      // fp32 x tiles (double buffered)
    uint32_t Ws[2][1024];             // weight fragments for one K-step (hi+lo)
    const float* xptr[MTILE];
    int   perm[MTILE];
    float w1T[LXD * LXD];
    float b0s[LXD], b1s[LXD], w2s[LXD];
    float b2s;
};

__device__ __forceinline__ void process_row(const Smem* S, const float* hrow,
                                            int row, float* __restrict__ out) {
    if (row < 0) return;
    float h2[LXD];
#pragma unroll
    for (int j = 0; j < LXD; ++j) h2[j] = S->b1s[j];
#pragma unroll
    for (int i = 0; i < LXD; ++i) {
        float xi = hrow[i] + S->b0s[i];
        xi = fminf(fmaxf(xi, 0.0f), 1.0f);
        const float* wr = &S->w1T[i * LXD];
#pragma unroll
        for (int j = 0; j < LXD; ++j) h2[j] = fmaf(xi, wr[j], h2[j]);
    }
    float o = S->b2s;
#pragma unroll
    for (int j = 0; j < LXD; ++j) {
        float c = fminf(fmaxf(h2[j], 0.0f), 1.0f);
        o = fmaf(c, S->w2s[j], o);
    }
    out[row] = o;
}

__device__ __forceinline__ void build_a(const float* xp, uint32_t ah[4], uint32_t al[4]) {
    float2 p0 = *reinterpret_cast<const float2*>(xp);                 // row g,   k lo
    float2 p1 = *reinterpret_cast<const float2*>(xp + 8 * XSTR);      // row g+8, k lo
    float2 p2 = *reinterpret_cast<const float2*>(xp + 8);             // row g,   k hi
    float2 p3 = *reinterpret_cast<const float2*>(xp + 8 * XSTR + 8);  // row g+8, k hi
    split2(p0, ah[0], al[0]);
    split2(p1, ah[1], al[1]);
    split2(p2, ah[2], al[2]);
    split2(p3, ah[3], al[3]);
}

__global__ void __launch_bounds__(NTHR, 2)
main_kernel(const float* __restrict__ x,
            const float* __restrict__ b0, const float* __restrict__ b1,
            const float* __restrict__ w1, const float* __restrict__ w2,
            const float* __restrict__ b2,
            float* __restrict__ out, int B) {
    extern __shared__ char smem_raw[];
    Smem* S = reinterpret_cast<Smem*>(smem_raw);

    const int tile = blockIdx.x;
    const int b    = blockIdx.y;
    const int cnt  = g_cnt[b];
    const int start = tile * MTILE;
    if (start >= cnt) return;

    const int t    = threadIdx.x;
    const int lane = t & 31;
    const int warp = t >> 5;
    const int g    = lane >> 2;      // row within 8-group
    const int tq   = lane & 3;       // k quad
    const int wrow = warp * 32;      // warp's 32-row slice

    // ---- stage per-CTA metadata + small weights ----
    {
        int gi = start + t;
        int ridx = (gi < cnt) ? g_list[b * MAXB + gi] : -1;
        S->perm[t] = ridx;
        S->xptr[t] = x + (size_t)(ridx < 0 ? 0 : ridx) * IN_DIM;
    }
    for (int idx = t; idx < LXD * LXD; idx += NTHR) {
        int i = idx >> 5, j = idx & 31;
        S->w1T[idx] = w1[(b * LXD + j) * LXD + i];
    }
    if (t < LXD) {
        S->b0s[t] = b0[b * LXD + t];
        S->b1s[t] = b1[b * LXD + t];
        S->w2s[t] = w2[b * LXD + t];
    }
    if (t == 32) S->b2s = b2[b];
    __syncthreads();

    const uint32_t* wfrag = g_Wfrag + ((size_t)(b * 32) << 10);
    const int k2 = t & 15;
    const int rb = t >> 4;

    auto load_step = [&](int stage, int s) {
        int k0 = s * BK;
#pragma unroll
        for (int p = 0; p < MTILE / 16; ++p) {
            int r = p * 16 + rb;
            cp8(&S->Xs[stage][r][k2 * 2], S->xptr[r] + k0 + k2 * 2);
        }
        cp16(&S->Ws[stage][t * 4], wfrag + (s << 10) + t * 4);
        cp_commit();
    };

    float c[2][4][4];
#pragma unroll
    for (int mf = 0; mf < 2; ++mf)
#pragma unroll
        for (int nf = 0; nf < 4; ++nf)
#pragma unroll
            for (int q = 0; q < 4; ++q) c[mf][nf][q] = 0.0f;

    load_step(0, 0);

#pragma unroll 1
    for (int s = 0; s < NSTEP; ++s) {
        const int stage = s & 1;
        if (s + 1 < NSTEP) {
            load_step(stage ^ 1, s + 1);
            cp_wait<1>();
        } else {
            cp_wait<0>();
        }
        __syncthreads();

#pragma unroll
        for (int kf = 0; kf < 2; ++kf) {
            uint32_t ah0[4], al0[4], ah1[4], al1[4];
            build_a(&S->Xs[stage][wrow + g][kf * 16 + 2 * tq], ah0, al0);
            build_a(&S->Xs[stage][wrow + 16 + g][kf * 16 + 2 * tq], ah1, al1);
            const uint32_t* wsb = S->Ws[stage];
#pragma unroll
            for (int nf = 0; nf < 4; ++nf) {
                uint2 bh = *reinterpret_cast<const uint2*>(wsb + (kf * 4 + nf) * 64 + lane * 2);
                uint2 bl = *reinterpret_cast<const uint2*>(wsb + ((2 + kf) * 4 + nf) * 64 + lane * 2);
                mma_bf16(c[0][nf], ah0, bh.x, bh.y);
                mma_bf16(c[0][nf], ah0, bl.x, bl.y);
                mma_bf16(c[0][nf], al0, bh.x, bh.y);
                mma_bf16(c[1][nf], ah1, bh.x, bh.y);
                mma_bf16(c[1][nf], ah1, bl.x, bl.y);
                mma_bf16(c[1][nf], al1, bh.x, bh.y);
            }
        }
        __syncthreads();
    }

    // ---- write layer-0 accumulators to smem (reuse Xs[0]) ----
    float (*Hs)[XSTR] = S->Xs[0];
#pragma unroll
    for (int mf = 0; mf < 2; ++mf)
#pragma unroll
        for (int nf = 0; nf < 4; ++nf) {
            int r0 = wrow + mf * 16 + g;
            int j0 = nf * 8 + 2 * tq;
            *reinterpret_cast<float2*>(&Hs[r0][j0]) =
                make_float2(c[mf][nf][0], c[mf][nf][1]);
            *reinterpret_cast<float2*>(&Hs[r0 + 8][j0]) =
                make_float2(c[mf][nf][2], c[mf][nf][3]);
        }
    __syncthreads();

    // ---- fused layer1 + layer2 epilogue (1 row / thread) ----
    process_row(S, Hs[t], S->perm[t], out);
}

// ---------------- launch ----------------
extern "C" void kernel_launch(void* const* d_in, const int* in_sizes, int n_in,
                              void* d_out, int out_size) {
    const float* x      = (const float*)d_in[0];
    const int*   ls     = (const int*)d_in[1];
    const float* w_fact = (const float*)d_in[2];
    const float* w0     = (const float*)d_in[3];
    const float* b0     = (const float*)d_in[4];
    const float* w1     = (const float*)d_in[5];
    const float* b1     = (const float*)d_in[6];
    const float* w2     = (const float*)d_in[7];
    const float* b2     = (const float*)d_in[8];
    float*       out    = (float*)d_out;

    const int B = in_sizes[0] / IN_DIM;

    prep_kernel<<<(NBUCK * LXD * 512 + 255) / 256, 256>>>(w0, w_fact);
    bin_kernel<<<(B + 255) / 256, 256>>>(ls, B);

    static const size_t smem_bytes = sizeof(Smem);
    cudaFuncSetAttribute(main_kernel, cudaFuncAttributeMaxDynamicSharedMemorySize,
                         (int)smem_bytes);
    dim3 grid((B + MTILE - 1) / MTILE, NBUCK);
    main_kernel<<<grid, NTHR, smem_bytes>>>(x, b0, b1, w1, w2, b2, out, B);
}

// round 5
// speedup vs baseline: 2.8275x; 1.1452x over previous
#include <cuda_runtime.h>
#include <cstdint>

#define IN_DIM 1024     // 2*L1
#define LXD    32
#define NBUCK  8
#define MAXB   65536
#define BK     32       // K per pipeline step
#define MTILE  128
#define NTHR   128
#define NSTEP  (IN_DIM / BK)   // 32
#define XSTR   40       // Xs row stride in floats (8B aligned, 2-way LDS conflict max)

// ---------------- device scratch ----------------
// Weight fragments: [b][step][split(hi/lo)][kf][nf][lane*2+r] as u32 bf16x2 pairs
__device__ uint32_t g_Wfrag[NBUCK * 32 * 2 * 2 * 4 * 64];   // 1 MB
__device__ int      g_cnt[NBUCK];
__device__ int      g_list[NBUCK * MAXB];

// ---------------- PTX helpers ----------------
__device__ __forceinline__ unsigned sptr(const void* p) {
    return (unsigned)__cvta_generic_to_shared(p);
}
__device__ __forceinline__ void cp16(void* dst, const void* src) {
    asm volatile("cp.async.cg.shared.global [%0], [%1], 16;\n" :: "r"(sptr(dst)), "l"(src));
}
__device__ __forceinline__ void cp_commit() { asm volatile("cp.async.commit_group;\n"); }
template<int N> __device__ __forceinline__ void cp_wait() {
    asm volatile("cp.async.wait_group %0;\n" :: "n"(N));
}
// pack two f32 -> bf16x2 (upper = hi_src, lower = lo_src)
__device__ __forceinline__ uint32_t cvt_pack(float hi_src, float lo_src) {
    uint32_t r;
    asm("cvt.rn.bf16x2.f32 %0, %1, %2;" : "=r"(r) : "f"(hi_src), "f"(lo_src));
    return r;
}
__device__ __forceinline__ void mma_bf16(float c[4], const uint32_t a[4],
                                         uint32_t b0, uint32_t b1) {
    asm("mma.sync.aligned.m16n8k16.row.col.f32.bf16.bf16.f32 "
        "{%0,%1,%2,%3},{%4,%5,%6,%7},{%8,%9},{%0,%1,%2,%3};"
        : "+f"(c[0]), "+f"(c[1]), "+f"(c[2]), "+f"(c[3])
        : "r"(a[0]), "r"(a[1]), "r"(a[2]), "r"(a[3]), "r"(b0), "r"(b1));
}
// split a float pair (p.x = k, p.y = k+1) into bf16x2 hi + bf16x2 lo
__device__ __forceinline__ void split2(float2 p, uint32_t& h, uint32_t& l) {
    h = cvt_pack(p.y, p.x);
    float e0 = p.x - __uint_as_float(h << 16);
    float e1 = p.y - __uint_as_float(h & 0xffff0000u);
    l = cvt_pack(e1, e0);
}

// ---------------- kernel 1: build bf16 hi/lo weight fragments + zero counters ----------------
__global__ void prep_kernel(const float* __restrict__ w0, const float* __restrict__ w_fact) {
    int tid = blockIdx.x * blockDim.x + threadIdx.x;   // NBUCK*LXD*512 = 131072
    if (tid < NBUCK * LXD * 512) {
        int kp = tid & 511;            // k pair index
        int j  = (tid >> 9) & 31;      // output column n
        int b  = tid >> 14;            // bucket
        int k0 = kp * 2;
        float x0 = w0[(b * LXD + j) * IN_DIM + k0]     + w_fact[j * IN_DIM + k0];
        float x1 = w0[(b * LXD + j) * IN_DIM + k0 + 1] + w_fact[j * IN_DIM + k0 + 1];
        uint32_t h, l;
        split2(make_float2(x0, x1), h, l);
        int step = k0 >> 5, kk = k0 & 31;
        int kf = kk >> 4, kr = kk & 15;
        int r = kr >> 3;
        int lane = ((j & 7) << 2) + ((kr & 7) >> 1);
        int nf = j >> 3;
        int base = ((((b * 32 + step) * 2 + 0) * 2 + kf) * 4 + nf) * 64 + lane * 2 + r;
        g_Wfrag[base]       = h;       // split 0 (hi)
        g_Wfrag[base + 512] = l;       // split 1 (lo), stride 2*4*64
    }
    if (blockIdx.x == 0 && threadIdx.x < NBUCK) g_cnt[threadIdx.x] = 0;
}

// ---------------- kernel 2: bin rows by bucket ----------------
// ls_indices is int32 on the wire (JAX x64 disabled).
__global__ void bin_kernel(const int* __restrict__ ls, int B) {
    int i = blockIdx.x * blockDim.x + threadIdx.x;
    if (i >= B) return;
    int b = ls[i] & (NBUCK - 1);
    unsigned active = __activemask();
    unsigned m = __match_any_sync(active, b);
    int lane = threadIdx.x & 31;
    int leader = __ffs(m) - 1;
    int rank = __popc(m & ((1u << lane) - 1u));
    int base = 0;
    if (lane == leader) base = atomicAdd(&g_cnt[b], __popc(m));
    base = __shfl_sync(m, base, leader);
    g_list[b * MAXB + base + rank] = i;
}

// ---------------- kernel 3: tensor-core binned GEMM + fused MLP ----------------
struct __align__(16) Smem {
    float    Xs[2][MTILE][XSTR];      // fp32 x tiles (double buffered)  40960 B
    uint32_t Ws[2][1024];             // weight fragments, one K-step (hi+lo)  8192 B
    const float* xptr[MTILE];
    int   perm[MTILE];
    float w1T[LXD * LXD];
    float b0s[LXD], b1s[LXD], w2s[LXD];
    float b2s;
};

__device__ __forceinline__ void process_row(const Smem* S, const float* hrow,
                                            int row, float* __restrict__ out) {
    if (row < 0) return;
    float h2[LXD];
#pragma unroll
    for (int j = 0; j < LXD; ++j) h2[j] = S->b1s[j];
#pragma unroll
    for (int i = 0; i < LXD; ++i) {
        float xi = hrow[i] + S->b0s[i];
        xi = fminf(fmaxf(xi, 0.0f), 1.0f);
        const float* wr = &S->w1T[i * LXD];
#pragma unroll
        for (int j = 0; j < LXD; ++j) h2[j] = fmaf(xi, wr[j], h2[j]);
    }
    float o = S->b2s;
#pragma unroll
    for (int j = 0; j < LXD; ++j) {
        float c = fminf(fmaxf(h2[j], 0.0f), 1.0f);
        o = fmaf(c, S->w2s[j], o);
    }
    out[row] = o;
}

__device__ __forceinline__ void build_a(const float* xp, uint32_t ah[4], uint32_t al[4]) {
    float2 p0 = *reinterpret_cast<const float2*>(xp);                 // row g,   k lo
    float2 p1 = *reinterpret_cast<const float2*>(xp + 8 * XSTR);      // row g+8, k lo
    float2 p2 = *reinterpret_cast<const float2*>(xp + 8);             // row g,   k hi
    float2 p3 = *reinterpret_cast<const float2*>(xp + 8 * XSTR + 8);  // row g+8, k hi
    split2(p0, ah[0], al[0]);
    split2(p1, ah[1], al[1]);
    split2(p2, ah[2], al[2]);
    split2(p3, ah[3], al[3]);
}

__global__ void __launch_bounds__(NTHR, 4)
main_kernel(const float* __restrict__ x,
            const float* __restrict__ b0, const float* __restrict__ b1,
            const float* __restrict__ w1, const float* __restrict__ w2,
            const float* __restrict__ b2,
            float* __restrict__ out, int B) {
    extern __shared__ char smem_raw[];
    Smem* S = reinterpret_cast<Smem*>(smem_raw);

    const int tile = blockIdx.x;
    const int b    = blockIdx.y;
    const int cnt  = g_cnt[b];
    const int start = tile * MTILE;
    if (start >= cnt) return;

    const int t    = threadIdx.x;
    const int lane = t & 31;
    const int warp = t >> 5;
    const int g    = lane >> 2;      // row within 8-group
    const int tq   = lane & 3;       // k quad
    const int wrow = warp * 32;      // warp's 32-row slice (4 warps x 32 = 128)

    // ---- stage per-CTA metadata + small weights ----
    {
        int gi = start + t;
        int ridx = (gi < cnt) ? g_list[b * MAXB + gi] : -1;
        S->perm[t] = ridx;
        S->xptr[t] = x + (size_t)(ridx < 0 ? 0 : ridx) * IN_DIM;
    }
    for (int idx = t; idx < LXD * LXD; idx += NTHR) {
        int i = idx >> 5, j = idx & 31;
        S->w1T[idx] = w1[(b * LXD + j) * LXD + i];
    }
    if (t < LXD) {
        S->b0s[t] = b0[b * LXD + t];
        S->b1s[t] = b1[b * LXD + t];
        S->w2s[t] = w2[b * LXD + t];
    }
    if (t == 32) S->b2s = b2[b];
    __syncthreads();

    const uint32_t* wfrag = g_Wfrag + ((size_t)(b * 32) << 10);
    const int k4 = t & 7;        // 8 x 16B chunks cover 128B (BK=32 floats)
    const int rb = t >> 3;       // 16 row-groups

    // ---- async loader for one K-step: x rows via cp16, weights via cp16 ----
    auto load_step = [&](int stage, int s) {
        int k0 = s * BK;
#pragma unroll
        for (int p = 0; p < MTILE / 16; ++p) {          // 8 rows per thread
            int r = p * 16 + rb;
            cp16(&S->Xs[stage][r][k4 * 4], S->xptr[r] + k0 + k4 * 4);
        }
        const uint32_t* wsrc = wfrag + (s << 10) + t * 8;
        uint32_t* wdst = &S->Ws[stage][t * 8];
        cp16(wdst, wsrc);
        cp16(wdst + 4, wsrc + 4);
        cp_commit();
    };

    float c[2][4][4];
#pragma unroll
    for (int mf = 0; mf < 2; ++mf)
#pragma unroll
        for (int nf = 0; nf < 4; ++nf)
#pragma unroll
            for (int q = 0; q < 4; ++q) c[mf][nf][q] = 0.0f;

    load_step(0, 0);

#pragma unroll 1
    for (int s = 0; s < NSTEP; ++s) {
        const int stage = s & 1;
        if (s + 1 < NSTEP) {
            load_step(stage ^ 1, s + 1);
            cp_wait<1>();
        } else {
            cp_wait<0>();
        }
        __syncthreads();

#pragma unroll
        for (int kf = 0; kf < 2; ++kf) {
            uint32_t ah0[4], al0[4], ah1[4], al1[4];
            build_a(&S->Xs[stage][wrow + g][kf * 16 + 2 * tq], ah0, al0);
            build_a(&S->Xs[stage][wrow + 16 + g][kf * 16 + 2 * tq], ah1, al1);
            const uint32_t* wsb = S->Ws[stage];
#pragma unroll
            for (int nf = 0; nf < 4; ++nf) {
                uint2 bh = *reinterpret_cast<const uint2*>(wsb + (kf * 4 + nf) * 64 + lane * 2);
                uint2 bl = *reinterpret_cast<const uint2*>(wsb + ((2 + kf) * 4 + nf) * 64 + lane * 2);
                mma_bf16(c[0][nf], ah0, bh.x, bh.y);
                mma_bf16(c[0][nf], ah0, bl.x, bl.y);
                mma_bf16(c[0][nf], al0, bh.x, bh.y);
                mma_bf16(c[1][nf], ah1, bh.x, bh.y);
                mma_bf16(c[1][nf], ah1, bl.x, bl.y);
                mma_bf16(c[1][nf], al1, bh.x, bh.y);
            }
        }
        __syncthreads();
    }

    // ---- write layer-0 accumulators to smem (reuse Xs[0]) ----
    float (*Hs)[XSTR] = S->Xs[0];
#pragma unroll
    for (int mf = 0; mf < 2; ++mf)
#pragma unroll
        for (int nf = 0; nf < 4; ++nf) {
            int r0 = wrow + mf * 16 + g;
            int j0 = nf * 8 + 2 * tq;
            *reinterpret_cast<float2*>(&Hs[r0][j0]) =
                make_float2(c[mf][nf][0], c[mf][nf][1]);
            *reinterpret_cast<float2*>(&Hs[r0 + 8][j0]) =
                make_float2(c[mf][nf][2], c[mf][nf][3]);
        }
    __syncthreads();

    // ---- fused layer1 + layer2 epilogue (1 row / thread) ----
    process_row(S, Hs[t], S->perm[t], out);
}

// ---------------- launch ----------------
extern "C" void kernel_launch(void* const* d_in, const int* in_sizes, int n_in,
                              void* d_out, int out_size) {
    const float* x      = (const float*)d_in[0];
    const int*   ls     = (const int*)d_in[1];
    const float* w_fact = (const float*)d_in[2];
    const float* w0     = (const float*)d_in[3];
    const float* b0     = (const float*)d_in[4];
    const float* w1     = (const float*)d_in[5];
    const float* b1     = (const float*)d_in[6];
    const float* w2     = (const float*)d_in[7];
    const float* b2     = (const float*)d_in[8];
    float*       out    = (float*)d_out;

    const int B = in_sizes[0] / IN_DIM;

    prep_kernel<<<(NBUCK * LXD * 512 + 255) / 256, 256>>>(w0, w_fact);
    bin_kernel<<<(B + 255) / 256, 256>>>(ls, B);

    static const size_t smem_bytes = sizeof(Smem);
    cudaFuncSetAttribute(main_kernel, cudaFuncAttributeMaxDynamicSharedMemorySize,
                         (int)smem_bytes);
    dim3 grid((B + MTILE - 1) / MTILE, NBUCK);
    main_kernel<<<grid, NTHR, smem_bytes>>>(x, b0, b1, w1, w2, b2, out, B);
}